// round 4
// baseline (speedup 1.0000x reference)
#include <cuda_runtime.h>
#include <math.h>

#define NN   40960
#define SS   4096
#define EE   81920
#define DD   64
#define HH   100
#define FIN  321
#define VV   50000

// ---------------- scratch (device globals; no allocation allowed) ----------------
__device__ float    g_x[NN * FIN];
__device__ float    g_xl[SS * FIN];
__device__ float    g_h[NN * HH];
__device__ float    g_msg[NN * HH];
__device__ float    g_gi[NN * 3 * HH];
__device__ float    g_gh[NN * 3 * HH];
__device__ int      g_deg[NN];
__device__ float    g_dinv[NN];
__device__ int      g_lastidx[SS];
__device__ float    g_last[SS * HH];
__device__ float    g_g1[NN * HH];
__device__ float    g_gate[NN];
__device__ float    g_w[NN];
__device__ unsigned g_gmax[SS];
__device__ float    g_wsum[SS];
__device__ float    g_pooled[SS * HH];

// ---------------- helpers ----------------
__device__ __forceinline__ unsigned enc_f(float f) {
    unsigned u = __float_as_uint(f);
    return (u & 0x80000000u) ? ~u : (u | 0x80000000u);
}
__device__ __forceinline__ float dec_f(unsigned e) {
    return (e & 0x80000000u) ? __uint_as_float(e ^ 0x80000000u) : __uint_as_float(~e);
}

// ---------------- init / zero ----------------
__global__ void k_init_small() {
    int i = blockIdx.x * blockDim.x + threadIdx.x;
    if (i < NN) g_deg[i] = 0;
    if (i < SS) { g_lastidx[i] = -1; g_gmax[i] = 0u; g_wsum[i] = 0.f; }
}
__global__ void k_zero_big() {
    int i = blockIdx.x * blockDim.x + threadIdx.x;
    if (i < NN * HH) g_msg[i] = 0.f;
    if (i < SS * HH) g_pooled[i] = 0.f;
}

// ---------------- node feature gather: x[n, 0..320] ----------------
__global__ void k_gather_x(const float* __restrict__ price,
                           const int* __restrict__ cat, const int* __restrict__ sub,
                           const int* __restrict__ elem, const int* __restrict__ brand,
                           const int* __restrict__ pid,
                           const float* __restrict__ ecat, const float* __restrict__ esub,
                           const float* __restrict__ eelem, const float* __restrict__ ebrand,
                           const float* __restrict__ eitem) {
    int n = blockIdx.x;
    int j = threadIdx.x;
    if (j >= FIN) return;
    float v;
    if (j == 0) {
        v = price[n];
    } else {
        int s = (j - 1) >> 6;
        int o = (j - 1) & 63;
        const float* tab;
        int idx;
        switch (s) {
            case 0:  tab = ecat;   idx = cat[n];   break;
            case 1:  tab = esub;   idx = sub[n];   break;
            case 2:  tab = eelem;  idx = elem[n];  break;
            case 3:  tab = ebrand; idx = brand[n]; break;
            default: tab = eitem;  idx = pid[n];   break;
        }
        v = tab[idx * DD + o];
    }
    g_x[n * FIN + j] = v;
}

// ---------------- generic tiled SGEMM: C = A[M,K] @ B[K,Nn] + bias, optional relu ----------------
__global__ void k_sgemm(const float* __restrict__ A, const float* __restrict__ B,
                        const float* __restrict__ bias, float* __restrict__ C,
                        int M, int Nn, int K, int relu) {
    __shared__ float As[64][17];
    __shared__ float Bs[16][64];
    int tid = threadIdx.x;
    int tx = tid & 15, ty = tid >> 4;
    int m0 = blockIdx.y * 64, n0 = blockIdx.x * 64;

    float acc[4][4];
#pragma unroll
    for (int i = 0; i < 4; i++)
#pragma unroll
        for (int j = 0; j < 4; j++) acc[i][j] = 0.f;

    for (int k0 = 0; k0 < K; k0 += 16) {
        for (int i = tid; i < 64 * 16; i += 256) {
            int mi = i >> 4, ki = i & 15;
            int m = m0 + mi, k = k0 + ki;
            As[mi][ki] = (m < M && k < K) ? A[m * K + k] : 0.f;
        }
        for (int i = tid; i < 16 * 64; i += 256) {
            int ki = i >> 6, ni = i & 63;
            int k = k0 + ki, n = n0 + ni;
            Bs[ki][ni] = (k < K && n < Nn) ? B[k * Nn + n] : 0.f;
        }
        __syncthreads();
#pragma unroll
        for (int k = 0; k < 16; k++) {
            float a0 = As[ty * 4 + 0][k];
            float a1 = As[ty * 4 + 1][k];
            float a2 = As[ty * 4 + 2][k];
            float a3 = As[ty * 4 + 3][k];
            float4 b = *(const float4*)&Bs[k][tx * 4];
            acc[0][0] += a0 * b.x; acc[0][1] += a0 * b.y; acc[0][2] += a0 * b.z; acc[0][3] += a0 * b.w;
            acc[1][0] += a1 * b.x; acc[1][1] += a1 * b.y; acc[1][2] += a1 * b.z; acc[1][3] += a1 * b.w;
            acc[2][0] += a2 * b.x; acc[2][1] += a2 * b.y; acc[2][2] += a2 * b.z; acc[2][3] += a2 * b.w;
            acc[3][0] += a3 * b.x; acc[3][1] += a3 * b.y; acc[3][2] += a3 * b.z; acc[3][3] += a3 * b.w;
        }
        __syncthreads();
    }

#pragma unroll
    for (int i = 0; i < 4; i++) {
        int m = m0 + ty * 4 + i;
        if (m >= M) continue;
#pragma unroll
        for (int j = 0; j < 4; j++) {
            int n = n0 + tx * 4 + j;
            if (n >= Nn) continue;
            float v = acc[i][j] + bias[n];
            if (relu) v = fmaxf(v, 0.f);
            C[m * Nn + n] = v;
        }
    }
}

// ---------------- degree + inverse ----------------
__global__ void k_deg(const int* __restrict__ eidx) {
    int e = blockIdx.x * blockDim.x + threadIdx.x;
    if (e < EE) atomicAdd(&g_deg[eidx[EE + e]], 1);
}
__global__ void k_dinv() {
    int n = blockIdx.x * blockDim.x + threadIdx.x;
    if (n < NN) g_dinv[n] = (g_deg[n] > 0) ? (1.f / (float)g_deg[n]) : 0.f;
}

// ---------------- edge scatter: msg[dst] += h[src] ----------------
__global__ void k_scatter(const int* __restrict__ eidx) {
    int e = blockIdx.x;
    int d = threadIdx.x;
    if (d >= HH) return;
    int s = eidx[e];
    int t = eidx[EE + e];
    atomicAdd(&g_msg[t * HH + d], g_h[s * HH + d]);
}
__global__ void k_scale_msg() {
    int i = blockIdx.x * blockDim.x + threadIdx.x;
    if (i < NN * HH) g_msg[i] *= g_dinv[i / HH];
}

// ---------------- GRU cell elementwise ----------------
__global__ void k_gru() {
    int i = blockIdx.x * blockDim.x + threadIdx.x;
    if (i >= NN * HH) return;
    int n = i / HH, j = i % HH;
    const float* gi = g_gi + n * 3 * HH;
    const float* gh = g_gh + n * 3 * HH;
    float r  = 1.f / (1.f + expf(-(gi[j] + gh[j])));
    float z  = 1.f / (1.f + expf(-(gi[HH + j] + gh[HH + j])));
    float nn = tanhf(gi[2 * HH + j] + r * gh[2 * HH + j]);
    float h  = g_h[i];
    g_h[i] = (1.f - z) * nn + z * h;
}

// ---------------- last index per session + gather ----------------
__global__ void k_lastidx(const int* __restrict__ batch) {
    int n = blockIdx.x * blockDim.x + threadIdx.x;
    if (n < NN) atomicMax(&g_lastidx[batch[n]], n);
}
__global__ void k_gather_xl() {
    int s = blockIdx.x;
    int j = threadIdx.x;
    if (j >= FIN) return;
    g_xl[s * FIN + j] = g_x[g_lastidx[s] * FIN + j];
}
__global__ void k_addlast(const int* __restrict__ batch) {
    int i = blockIdx.x * blockDim.x + threadIdx.x;
    if (i >= NN * HH) return;
    g_h[i] += g_last[batch[i / HH] * HH + i % HH];
}

// ---------------- attention gate: gate = g1 . W_g2 + b_g2 ; gmax ----------------
__global__ void k_gate(const float* __restrict__ wg2, const float* __restrict__ bg2,
                       const int* __restrict__ batch) {
    int w = (blockIdx.x * blockDim.x + threadIdx.x) >> 5;
    int lane = threadIdx.x & 31;
    if (w >= NN) return;
    const float* row = g_g1 + w * HH;
    float s = 0.f;
    for (int k = lane; k < HH; k += 32) s += row[k] * wg2[k];
#pragma unroll
    for (int o = 16; o; o >>= 1) s += __shfl_xor_sync(0xffffffffu, s, o);
    if (lane == 0) {
        float g = s + bg2[0];
        g_gate[w] = g;
        atomicMax(&g_gmax[batch[w]], enc_f(g));
    }
}
__global__ void k_softw(const int* __restrict__ batch) {
    int n = blockIdx.x * blockDim.x + threadIdx.x;
    if (n >= NN) return;
    int b = batch[n];
    float wv = expf(g_gate[n] - dec_f(g_gmax[b]));
    g_w[n] = wv;
    atomicAdd(&g_wsum[b], wv);
}
__global__ void k_pool(const int* __restrict__ batch) {
    int n = blockIdx.x;
    int d = threadIdx.x;
    if (d >= HH) return;
    int b = batch[n];
    float alpha = g_w[n] / g_wsum[b];
    atomicAdd(&g_pooled[b * HH + d], alpha * g_h[n * HH + d]);
}

// ---------------- specialized FC: out[4096,50000] = pooled @ W_fc + b_fc ----------------
// B panel (100x128) + A chunk (64x100) resident in smem; 4x8 register tile.
__global__ void k_fc(const float* __restrict__ W, const float* __restrict__ bias,
                     float* __restrict__ C) {
    extern __shared__ float sm[];
    float* Bs = sm;               // [100][128]
    float* As = sm + HH * 128;    // [64][100]
    int tid = threadIdx.x;
    int tx = tid & 15, ty = tid >> 4;
    int n0 = blockIdx.x * 128;

    for (int i = tid; i < HH * 128; i += 256) {
        int k = i >> 7, c = i & 127;
        int n = n0 + c;
        Bs[i] = (n < VV) ? W[k * VV + n] : 0.f;
    }
    float br[8];
#pragma unroll
    for (int j = 0; j < 8; j++) {
        int n = n0 + tx * 8 + j;
        br[j] = (n < VV) ? bias[n] : 0.f;
    }

    for (int chunk = 0; chunk < 16; chunk++) {
        int m0 = blockIdx.y * 1024 + chunk * 64;
        __syncthreads();
        for (int i = tid; i < 64 * HH; i += 256) As[i] = g_pooled[m0 * HH + i];
        __syncthreads();

        float acc[4][8];
#pragma unroll
        for (int i = 0; i < 4; i++)
#pragma unroll
            for (int j = 0; j < 8; j++) acc[i][j] = 0.f;

#pragma unroll 4
        for (int k = 0; k < HH; k++) {
            float a0 = As[(ty * 4 + 0) * HH + k];
            float a1 = As[(ty * 4 + 1) * HH + k];
            float a2 = As[(ty * 4 + 2) * HH + k];
            float a3 = As[(ty * 4 + 3) * HH + k];
            float4 b0 = *(const float4*)&Bs[k * 128 + tx * 8];
            float4 b1 = *(const float4*)&Bs[k * 128 + tx * 8 + 4];
            acc[0][0] += a0 * b0.x; acc[0][1] += a0 * b0.y; acc[0][2] += a0 * b0.z; acc[0][3] += a0 * b0.w;
            acc[0][4] += a0 * b1.x; acc[0][5] += a0 * b1.y; acc[0][6] += a0 * b1.z; acc[0][7] += a0 * b1.w;
            acc[1][0] += a1 * b0.x; acc[1][1] += a1 * b0.y; acc[1][2] += a1 * b0.z; acc[1][3] += a1 * b0.w;
            acc[1][4] += a1 * b1.x; acc[1][5] += a1 * b1.y; acc[1][6] += a1 * b1.z; acc[1][7] += a1 * b1.w;
            acc[2][0] += a2 * b0.x; acc[2][1] += a2 * b0.y; acc[2][2] += a2 * b0.z; acc[2][3] += a2 * b0.w;
            acc[2][4] += a2 * b1.x; acc[2][5] += a2 * b1.y; acc[2][6] += a2 * b1.z; acc[2][7] += a2 * b1.w;
            acc[3][0] += a3 * b0.x; acc[3][1] += a3 * b0.y; acc[3][2] += a3 * b0.z; acc[3][3] += a3 * b0.w;
            acc[3][4] += a3 * b1.x; acc[3][5] += a3 * b1.y; acc[3][6] += a3 * b1.z; acc[3][7] += a3 * b1.w;
        }

#pragma unroll
        for (int i = 0; i < 4; i++) {
            int m = m0 + ty * 4 + i;
            size_t base = (size_t)m * VV + n0 + tx * 8;
            if (n0 + tx * 8 + 7 < VV) {
                float4 v0 = make_float4(acc[i][0] + br[0], acc[i][1] + br[1],
                                        acc[i][2] + br[2], acc[i][3] + br[3]);
                float4 v1 = make_float4(acc[i][4] + br[4], acc[i][5] + br[5],
                                        acc[i][6] + br[6], acc[i][7] + br[7]);
                *(float4*)&C[base] = v0;
                *(float4*)&C[base + 4] = v1;
            } else {
#pragma unroll
                for (int j = 0; j < 8; j++) {
                    int n = n0 + tx * 8 + j;
                    if (n < VV) C[base + j] = acc[i][j] + br[j];
                }
            }
        }
    }
}

// ---------------- launch ----------------
extern "C" void kernel_launch(void* const* d_in, const int* in_sizes, int n_in,
                              void* d_out, int out_size) {
    const float* price    = (const float*)d_in[0];
    const int*   category = (const int*)d_in[1];
    const int*   sub      = (const int*)d_in[2];
    const int*   elem     = (const int*)d_in[3];
    const int*   brand    = (const int*)d_in[4];
    const int*   pid      = (const int*)d_in[5];
    const int*   eidx     = (const int*)d_in[6];
    const int*   batch    = (const int*)d_in[7];
    const float* ecat     = (const float*)d_in[8];
    const float* esub     = (const float*)d_in[9];
    const float* eelem    = (const float*)d_in[10];
    const float* ebrand   = (const float*)d_in[11];
    const float* eitem    = (const float*)d_in[12];
    const float* W_msg    = (const float*)d_in[13];
    const float* b_msg    = (const float*)d_in[14];
    const float* W_ih     = (const float*)d_in[15];
    const float* W_hh     = (const float*)d_in[16];
    const float* b_ih     = (const float*)d_in[17];
    const float* b_hh     = (const float*)d_in[18];
    const float* W_last   = (const float*)d_in[19];
    const float* b_last   = (const float*)d_in[20];
    const float* W_g1     = (const float*)d_in[21];
    const float* b_g1     = (const float*)d_in[22];
    const float* W_g2     = (const float*)d_in[23];
    const float* b_g2     = (const float*)d_in[24];
    const float* W_fc     = (const float*)d_in[25];
    const float* b_fc     = (const float*)d_in[26];
    float* out = (float*)d_out;

    float *p_x, *p_xl, *p_h, *p_msg, *p_gi, *p_gh, *p_last, *p_g1;
    cudaGetSymbolAddress((void**)&p_x,    g_x);
    cudaGetSymbolAddress((void**)&p_xl,   g_xl);
    cudaGetSymbolAddress((void**)&p_h,    g_h);
    cudaGetSymbolAddress((void**)&p_msg,  g_msg);
    cudaGetSymbolAddress((void**)&p_gi,   g_gi);
    cudaGetSymbolAddress((void**)&p_gh,   g_gh);
    cudaGetSymbolAddress((void**)&p_last, g_last);
    cudaGetSymbolAddress((void**)&p_g1,   g_g1);

    cudaFuncSetAttribute(k_fc, cudaFuncAttributeMaxDynamicSharedMemorySize, 76800);

    // init scratch
    k_init_small<<<(NN + 255) / 256, 256>>>();
    k_zero_big<<<(NN * HH + 255) / 256, 256>>>();

    // node features
    k_gather_x<<<NN, 352>>>(price, category, sub, elem, brand, pid,
                            ecat, esub, eelem, ebrand, eitem);

    // h0 = x @ W_msg + b_msg
    {
        dim3 g((HH + 63) / 64, (NN + 63) / 64);
        k_sgemm<<<g, 256>>>(p_x, W_msg, b_msg, p_h, NN, HH, FIN, 0);
    }

    // degrees
    k_deg<<<(EE + 255) / 256, 256>>>(eidx);
    k_dinv<<<(NN + 255) / 256, 256>>>();

    // mean aggregation
    k_scatter<<<EE, 128>>>(eidx);
    k_scale_msg<<<(NN * HH + 255) / 256, 256>>>();

    // GRU gates
    {
        dim3 g((3 * HH + 63) / 64, (NN + 63) / 64);
        k_sgemm<<<g, 256>>>(p_msg, W_ih, b_ih, p_gi, NN, 3 * HH, HH, 0);
        k_sgemm<<<g, 256>>>(p_h,   W_hh, b_hh, p_gh, NN, 3 * HH, HH, 0);
    }
    k_gru<<<(NN * HH + 255) / 256, 256>>>();

    // last node per session
    k_lastidx<<<(NN + 255) / 256, 256>>>(batch);
    k_gather_xl<<<SS, 352>>>();
    {
        dim3 g((HH + 63) / 64, (SS + 63) / 64);
        k_sgemm<<<g, 256>>>(p_xl, W_last, b_last, p_last, SS, HH, FIN, 0);
    }
    k_addlast<<<(NN * HH + 255) / 256, 256>>>(batch);

    // attention gate MLP
    {
        dim3 g((HH + 63) / 64, (NN + 63) / 64);
        k_sgemm<<<g, 256>>>(p_h, W_g1, b_g1, p_g1, NN, HH, HH, 1);
    }
    k_gate<<<(NN * 32 + 255) / 256, 256>>>(W_g2, b_g2, batch);
    k_softw<<<(NN + 255) / 256, 256>>>(batch);
    k_pool<<<NN, 128>>>(batch);

    // final scoring
    {
        dim3 g((VV + 127) / 128, 4);
        k_fc<<<g, 256, 76800>>>(W_fc, b_fc, out);
    }
}

// round 5
// speedup vs baseline: 1.3203x; 1.3203x over previous
#include <cuda_runtime.h>
#include <math.h>

#define NN   40960
#define SS   4096
#define EE   81920
#define DD   64
#define HH   100
#define FIN  321
#define VV   50000

// ---------------- scratch (device globals; no allocation allowed) ----------------
__device__ float    g_x[NN * FIN];
__device__ float    g_xl[SS * FIN];
__device__ float    g_h[NN * HH];
__device__ float    g_msg[NN * HH];
__device__ float    g_gi[NN * 3 * HH];
__device__ float    g_gh[NN * 3 * HH];
__device__ int      g_deg[NN];
__device__ float    g_dinv[NN];
__device__ int      g_lastidx[SS];
__device__ float    g_last[SS * HH];
__device__ float    g_g1[NN * HH];
__device__ float    g_gate[NN];
__device__ float    g_w[NN];
__device__ unsigned g_gmax[SS];
__device__ float    g_wsum[SS];
__device__ float    g_pooled[SS * HH];

// ---------------- f32x2 packed-math helpers (Blackwell FFMA2) ----------------
__device__ __forceinline__ unsigned long long f2_pack(float lo, float hi) {
    unsigned long long r;
    asm("mov.b64 %0, {%1, %2};" : "=l"(r) : "f"(lo), "f"(hi));
    return r;
}
__device__ __forceinline__ float2 f2_unpack(unsigned long long v) {
    float lo, hi;
    asm("mov.b64 {%0, %1}, %2;" : "=f"(lo), "=f"(hi) : "l"(v));
    return make_float2(lo, hi);
}
__device__ __forceinline__ unsigned long long f2_fma(unsigned long long a,
                                                     unsigned long long b,
                                                     unsigned long long c) {
    asm("fma.rn.f32x2 %0, %1, %2, %3;" : "=l"(c) : "l"(a), "l"(b), "l"(c));
    return c;
}

// ---------------- helpers ----------------
__device__ __forceinline__ unsigned enc_f(float f) {
    unsigned u = __float_as_uint(f);
    return (u & 0x80000000u) ? ~u : (u | 0x80000000u);
}
__device__ __forceinline__ float dec_f(unsigned e) {
    return (e & 0x80000000u) ? __uint_as_float(e ^ 0x80000000u) : __uint_as_float(~e);
}

// ---------------- init / zero ----------------
__global__ void k_init_small() {
    int i = blockIdx.x * blockDim.x + threadIdx.x;
    if (i < NN) g_deg[i] = 0;
    if (i < SS) { g_lastidx[i] = -1; g_gmax[i] = 0u; g_wsum[i] = 0.f; }
}
__global__ void k_zero_big() {
    int i = blockIdx.x * blockDim.x + threadIdx.x;
    if (i < NN * HH) g_msg[i] = 0.f;
    if (i < SS * HH) g_pooled[i] = 0.f;
}

// ---------------- node feature gather: x[n, 0..320] ----------------
__global__ void k_gather_x(const float* __restrict__ price,
                           const int* __restrict__ cat, const int* __restrict__ sub,
                           const int* __restrict__ elem, const int* __restrict__ brand,
                           const int* __restrict__ pid,
                           const float* __restrict__ ecat, const float* __restrict__ esub,
                           const float* __restrict__ eelem, const float* __restrict__ ebrand,
                           const float* __restrict__ eitem) {
    int n = blockIdx.x;
    int j = threadIdx.x;
    if (j >= FIN) return;
    float v;
    if (j == 0) {
        v = price[n];
    } else {
        int s = (j - 1) >> 6;
        int o = (j - 1) & 63;
        const float* tab;
        int idx;
        switch (s) {
            case 0:  tab = ecat;   idx = cat[n];   break;
            case 1:  tab = esub;   idx = sub[n];   break;
            case 2:  tab = eelem;  idx = elem[n];  break;
            case 3:  tab = ebrand; idx = brand[n]; break;
            default: tab = eitem;  idx = pid[n];   break;
        }
        v = tab[idx * DD + o];
    }
    g_x[n * FIN + j] = v;
}

// ---------------- tiled SGEMM: C = A[M,K] @ B[K,Nn] + bias, optional relu ----------------
// 128x64 block tile, 8x4 per-thread register tile.
__global__ void k_sgemm(const float* __restrict__ A, const float* __restrict__ B,
                        const float* __restrict__ bias, float* __restrict__ C,
                        int M, int Nn, int K, int relu) {
    __shared__ float As[128][17];
    __shared__ float Bs[16][64];
    int tid = threadIdx.x;
    int tx = tid & 15, ty = tid >> 4;     // tx: 4 cols each, ty: 8 rows each
    int m0 = blockIdx.y * 128, n0 = blockIdx.x * 64;

    float acc[8][4];
#pragma unroll
    for (int i = 0; i < 8; i++)
#pragma unroll
        for (int j = 0; j < 4; j++) acc[i][j] = 0.f;

    for (int k0 = 0; k0 < K; k0 += 16) {
        // load A tile: 128x16 = 2048 elems, 8 per thread
        for (int i = tid; i < 128 * 16; i += 256) {
            int mi = i >> 4, ki = i & 15;
            int m = m0 + mi, k = k0 + ki;
            As[mi][ki] = (m < M && k < K) ? A[m * K + k] : 0.f;
        }
        // load B tile: 16x64 = 1024 elems, 4 per thread
        for (int i = tid; i < 16 * 64; i += 256) {
            int ki = i >> 6, ni = i & 63;
            int k = k0 + ki, n = n0 + ni;
            Bs[ki][ni] = (k < K && n < Nn) ? B[k * Nn + n] : 0.f;
        }
        __syncthreads();
#pragma unroll
        for (int k = 0; k < 16; k++) {
            float a[8];
#pragma unroll
            for (int i = 0; i < 8; i++) a[i] = As[ty * 8 + i][k];
            float4 b = *(const float4*)&Bs[k][tx * 4];
#pragma unroll
            for (int i = 0; i < 8; i++) {
                acc[i][0] += a[i] * b.x;
                acc[i][1] += a[i] * b.y;
                acc[i][2] += a[i] * b.z;
                acc[i][3] += a[i] * b.w;
            }
        }
        __syncthreads();
    }

#pragma unroll
    for (int i = 0; i < 8; i++) {
        int m = m0 + ty * 8 + i;
        if (m >= M) continue;
#pragma unroll
        for (int j = 0; j < 4; j++) {
            int n = n0 + tx * 4 + j;
            if (n >= Nn) continue;
            float v = acc[i][j] + bias[n];
            if (relu) v = fmaxf(v, 0.f);
            C[m * Nn + n] = v;
        }
    }
}

// ---------------- degree + inverse ----------------
__global__ void k_deg(const int* __restrict__ eidx) {
    int e = blockIdx.x * blockDim.x + threadIdx.x;
    if (e < EE) atomicAdd(&g_deg[eidx[EE + e]], 1);
}
__global__ void k_dinv() {
    int n = blockIdx.x * blockDim.x + threadIdx.x;
    if (n < NN) g_dinv[n] = (g_deg[n] > 0) ? (1.f / (float)g_deg[n]) : 0.f;
}

// ---------------- edge scatter: msg[dst] += h[src] ----------------
__global__ void k_scatter(const int* __restrict__ eidx) {
    int e = blockIdx.x;
    int d = threadIdx.x;
    if (d >= HH) return;
    int s = eidx[e];
    int t = eidx[EE + e];
    atomicAdd(&g_msg[t * HH + d], g_h[s * HH + d]);
}
__global__ void k_scale_msg() {
    int i = blockIdx.x * blockDim.x + threadIdx.x;
    if (i < NN * HH) g_msg[i] *= g_dinv[i / HH];
}

// ---------------- GRU cell elementwise ----------------
__global__ void k_gru() {
    int i = blockIdx.x * blockDim.x + threadIdx.x;
    if (i >= NN * HH) return;
    int n = i / HH, j = i % HH;
    const float* gi = g_gi + n * 3 * HH;
    const float* gh = g_gh + n * 3 * HH;
    float r  = 1.f / (1.f + expf(-(gi[j] + gh[j])));
    float z  = 1.f / (1.f + expf(-(gi[HH + j] + gh[HH + j])));
    float nn = tanhf(gi[2 * HH + j] + r * gh[2 * HH + j]);
    float h  = g_h[i];
    g_h[i] = (1.f - z) * nn + z * h;
}

// ---------------- last index per session + gather ----------------
__global__ void k_lastidx(const int* __restrict__ batch) {
    int n = blockIdx.x * blockDim.x + threadIdx.x;
    if (n < NN) atomicMax(&g_lastidx[batch[n]], n);
}
__global__ void k_gather_xl() {
    int s = blockIdx.x;
    int j = threadIdx.x;
    if (j >= FIN) return;
    g_xl[s * FIN + j] = g_x[g_lastidx[s] * FIN + j];
}
__global__ void k_addlast(const int* __restrict__ batch) {
    int i = blockIdx.x * blockDim.x + threadIdx.x;
    if (i >= NN * HH) return;
    g_h[i] += g_last[batch[i / HH] * HH + i % HH];
}

// ---------------- attention gate ----------------
__global__ void k_gate(const float* __restrict__ wg2, const float* __restrict__ bg2,
                       const int* __restrict__ batch) {
    int w = (blockIdx.x * blockDim.x + threadIdx.x) >> 5;
    int lane = threadIdx.x & 31;
    if (w >= NN) return;
    const float* row = g_g1 + w * HH;
    float s = 0.f;
    for (int k = lane; k < HH; k += 32) s += row[k] * wg2[k];
#pragma unroll
    for (int o = 16; o; o >>= 1) s += __shfl_xor_sync(0xffffffffu, s, o);
    if (lane == 0) {
        float g = s + bg2[0];
        g_gate[w] = g;
        atomicMax(&g_gmax[batch[w]], enc_f(g));
    }
}
__global__ void k_softw(const int* __restrict__ batch) {
    int n = blockIdx.x * blockDim.x + threadIdx.x;
    if (n >= NN) return;
    int b = batch[n];
    float wv = expf(g_gate[n] - dec_f(g_gmax[b]));
    g_w[n] = wv;
    atomicAdd(&g_wsum[b], wv);
}
__global__ void k_pool(const int* __restrict__ batch) {
    int n = blockIdx.x;
    int d = threadIdx.x;
    if (d >= HH) return;
    int b = batch[n];
    float alpha = g_w[n] / g_wsum[b];
    atomicAdd(&g_pooled[b * HH + d], alpha * g_h[n * HH + d]);
}

// ---------------- specialized FC (f32x2 packed): out[4096,50000] = pooled @ W_fc + b_fc ----------
// Block tile: 128 cols x 128 rows per chunk, 4 chunks. Per thread: 8 rows x 8 cols
// as 8x4 f32x2 accumulators (column pairs). B pairs come free from contiguous Bs;
// A is broadcast-packed (a,a) once per row per k.
__global__ void __launch_bounds__(256, 2)
k_fc(const float* __restrict__ W, const float* __restrict__ bias,
     float* __restrict__ C) {
    extern __shared__ float sm[];
    float* Bs = sm;                   // [100][128]
    float* As = sm + HH * 128;        // [128][101] (padded: +1 to dodge bank conflicts)
    int tid = threadIdx.x;
    int tx = tid & 15, ty = tid >> 4; // tx: 8 cols, ty: 8 rows
    int n0 = blockIdx.x * 128;

    for (int i = tid; i < HH * 128; i += 256) {
        int k = i >> 7, c = i & 127;
        int n = n0 + c;
        Bs[i] = (n < VV) ? W[k * VV + n] : 0.f;
    }
    float br[8];
#pragma unroll
    for (int j = 0; j < 8; j++) {
        int n = n0 + tx * 8 + j;
        br[j] = (n < VV) ? bias[n] : 0.f;
    }

    for (int chunk = 0; chunk < 4; chunk++) {
        int m0 = blockIdx.y * 512 + chunk * 128;
        __syncthreads();
        for (int i = tid; i < 128 * HH; i += 256) {
            int r = i / HH, k = i - r * HH;
            As[r * 101 + k] = g_pooled[m0 * HH + i];
        }
        __syncthreads();

        unsigned long long acc[8][4];
#pragma unroll
        for (int i = 0; i < 8; i++)
#pragma unroll
            for (int j = 0; j < 4; j++) acc[i][j] = 0ull;

#pragma unroll 2
        for (int k = 0; k < HH; k++) {
            unsigned long long ap[8];
#pragma unroll
            for (int i = 0; i < 8; i++) {
                float a = As[(ty * 8 + i) * 101 + k];
                ap[i] = f2_pack(a, a);
            }
            ulonglong2 b01 = *(const ulonglong2*)&Bs[k * 128 + tx * 8];
            ulonglong2 b23 = *(const ulonglong2*)&Bs[k * 128 + tx * 8 + 4];
#pragma unroll
            for (int i = 0; i < 8; i++) {
                acc[i][0] = f2_fma(ap[i], b01.x, acc[i][0]);
                acc[i][1] = f2_fma(ap[i], b01.y, acc[i][1]);
                acc[i][2] = f2_fma(ap[i], b23.x, acc[i][2]);
                acc[i][3] = f2_fma(ap[i], b23.y, acc[i][3]);
            }
        }

#pragma unroll
        for (int i = 0; i < 8; i++) {
            int m = m0 + ty * 8 + i;
            size_t base = (size_t)m * VV + n0 + tx * 8;
            float2 p0 = f2_unpack(acc[i][0]);
            float2 p1 = f2_unpack(acc[i][1]);
            float2 p2 = f2_unpack(acc[i][2]);
            float2 p3 = f2_unpack(acc[i][3]);
            if (n0 + tx * 8 + 7 < VV) {
                float4 v0 = make_float4(p0.x + br[0], p0.y + br[1],
                                        p1.x + br[2], p1.y + br[3]);
                float4 v1 = make_float4(p2.x + br[4], p2.y + br[5],
                                        p3.x + br[6], p3.y + br[7]);
                *(float4*)&C[base] = v0;
                *(float4*)&C[base + 4] = v1;
            } else {
                float vals[8] = {p0.x, p0.y, p1.x, p1.y, p2.x, p2.y, p3.x, p3.y};
#pragma unroll
                for (int j = 0; j < 8; j++) {
                    int n = n0 + tx * 8 + j;
                    if (n < VV) C[base + j] = vals[j] + br[j];
                }
            }
        }
    }
}

// ---------------- launch ----------------
extern "C" void kernel_launch(void* const* d_in, const int* in_sizes, int n_in,
                              void* d_out, int out_size) {
    const float* price    = (const float*)d_in[0];
    const int*   category = (const int*)d_in[1];
    const int*   sub      = (const int*)d_in[2];
    const int*   elem     = (const int*)d_in[3];
    const int*   brand    = (const int*)d_in[4];
    const int*   pid      = (const int*)d_in[5];
    const int*   eidx     = (const int*)d_in[6];
    const int*   batch    = (const int*)d_in[7];
    const float* ecat     = (const float*)d_in[8];
    const float* esub     = (const float*)d_in[9];
    const float* eelem    = (const float*)d_in[10];
    const float* ebrand   = (const float*)d_in[11];
    const float* eitem    = (const float*)d_in[12];
    const float* W_msg    = (const float*)d_in[13];
    const float* b_msg    = (const float*)d_in[14];
    const float* W_ih     = (const float*)d_in[15];
    const float* W_hh     = (const float*)d_in[16];
    const float* b_ih     = (const float*)d_in[17];
    const float* b_hh     = (const float*)d_in[18];
    const float* W_last   = (const float*)d_in[19];
    const float* b_last   = (const float*)d_in[20];
    const float* W_g1     = (const float*)d_in[21];
    const float* b_g1     = (const float*)d_in[22];
    const float* W_g2     = (const float*)d_in[23];
    const float* b_g2     = (const float*)d_in[24];
    const float* W_fc     = (const float*)d_in[25];
    const float* b_fc     = (const float*)d_in[26];
    float* out = (float*)d_out;

    float *p_x, *p_xl, *p_h, *p_msg, *p_gi, *p_gh, *p_last, *p_g1;
    cudaGetSymbolAddress((void**)&p_x,    g_x);
    cudaGetSymbolAddress((void**)&p_xl,   g_xl);
    cudaGetSymbolAddress((void**)&p_h,    g_h);
    cudaGetSymbolAddress((void**)&p_msg,  g_msg);
    cudaGetSymbolAddress((void**)&p_gi,   g_gi);
    cudaGetSymbolAddress((void**)&p_gh,   g_gh);
    cudaGetSymbolAddress((void**)&p_last, g_last);
    cudaGetSymbolAddress((void**)&p_g1,   g_g1);

    // Bs 100*128*4 = 51200 + As 128*101*4 = 51712 -> 102912 bytes
    cudaFuncSetAttribute(k_fc, cudaFuncAttributeMaxDynamicSharedMemorySize, 102912);

    // init scratch
    k_init_small<<<(NN + 255) / 256, 256>>>();
    k_zero_big<<<(NN * HH + 255) / 256, 256>>>();

    // node features
    k_gather_x<<<NN, 352>>>(price, category, sub, elem, brand, pid,
                            ecat, esub, eelem, ebrand, eitem);

    // h0 = x @ W_msg + b_msg
    {
        dim3 g((HH + 63) / 64, (NN + 127) / 128);
        k_sgemm<<<g, 256>>>(p_x, W_msg, b_msg, p_h, NN, HH, FIN, 0);
    }

    // degrees
    k_deg<<<(EE + 255) / 256, 256>>>(eidx);
    k_dinv<<<(NN + 255) / 256, 256>>>();

    // mean aggregation
    k_scatter<<<EE, 128>>>(eidx);
    k_scale_msg<<<(NN * HH + 255) / 256, 256>>>();

    // GRU gates
    {
        dim3 g((3 * HH + 63) / 64, (NN + 127) / 128);
        k_sgemm<<<g, 256>>>(p_msg, W_ih, b_ih, p_gi, NN, 3 * HH, HH, 0);
        k_sgemm<<<g, 256>>>(p_h,   W_hh, b_hh, p_gh, NN, 3 * HH, HH, 0);
    }
    k_gru<<<(NN * HH + 255) / 256, 256>>>();

    // last node per session
    k_lastidx<<<(NN + 255) / 256, 256>>>(batch);
    k_gather_xl<<<SS, 352>>>();
    {
        dim3 g((HH + 63) / 64, (SS + 127) / 128);
        k_sgemm<<<g, 256>>>(p_xl, W_last, b_last, p_last, SS, HH, FIN, 0);
    }
    k_addlast<<<(NN * HH + 255) / 256, 256>>>(batch);

    // attention gate MLP
    {
        dim3 g((HH + 63) / 64, (NN + 127) / 128);
        k_sgemm<<<g, 256>>>(p_h, W_g1, b_g1, p_g1, NN, HH, HH, 1);
    }
    k_gate<<<(NN * 32 + 255) / 256, 256>>>(W_g2, b_g2, batch);
    k_softw<<<(NN + 255) / 256, 256>>>(batch);
    k_pool<<<NN, 128>>>(batch);

    // final scoring: grid (ceil(50000/128), 4096/512)
    {
        dim3 g((VV + 127) / 128, 8);
        k_fc<<<g, 256, 102912>>>(W_fc, b_fc, out);
    }
}